// round 4
// baseline (speedup 1.0000x reference)
#include <cuda_runtime.h>

#define NN 50000
#define NEMAX 1000000
#define NB 196          // ceil(NN/256)

// ---------------- scratch ----------------
// floats: [nsrc NN | ndst NN | y1 64NN | agg1 64NN | h1 64NN | p2 32NN | agg2 32NN | p3 16NN]
__device__ __align__(256) float g_work[274 * NN];
// ints:   [ideg NN | odeg NN | rowptr NN+1 | cursor NN | part 256 | partpre 256 | csr NEMAX]
__device__ __align__(256) int g_int[4 * NN + 1 + 512 + NEMAX];

#define OFF_NSRC 0
#define OFF_NDST (NN)
#define OFF_Y1   (2 * NN)
#define OFF_AGG1 (66 * NN)
#define OFF_H1   (130 * NN)
#define OFF_P2   (194 * NN)
#define OFF_AGG2 (226 * NN)
#define OFF_P3   (258 * NN)

#define IOFF_IDEG 0
#define IOFF_ODEG (NN)
#define IOFF_ROWP (2 * NN)
#define IOFF_CUR  (3 * NN + 1)
#define IOFF_PART (4 * NN + 1)
#define IOFF_PPRE (4 * NN + 1 + 256)
#define IOFF_CSR  (4 * NN + 1 + 512)

// ---------------- degree / norm / CSR ----------------

__global__ void k_zero_deg() {
    int i = blockIdx.x * blockDim.x + threadIdx.x;
    if (i < 2 * NN) g_int[i] = 0;
}

__global__ void k_deg(const int* __restrict__ src, const int* __restrict__ dst, int E) {
    int e = blockIdx.x * blockDim.x + threadIdx.x;
    if (e < E) {
        atomicAdd(&g_int[IOFF_ODEG + src[e]], 1);
        atomicAdd(&g_int[IOFF_IDEG + dst[e]], 1);
    }
}

// fused: norms for both degree vectors + per-block partial sums of in_deg
__global__ void k_norm_scan1() {
    __shared__ int sh[256];
    int i = blockIdx.x * 256 + threadIdx.x;
    int idv = 0;
    if (i < NN) {
        idv = g_int[IOFF_IDEG + i];
        int odv = g_int[IOFF_ODEG + i];
        g_work[OFF_NSRC + i] = rsqrtf(fmaxf((float)odv, 1.0f));
        g_work[OFF_NDST + i] = rsqrtf(fmaxf((float)idv, 1.0f));
    }
    sh[threadIdx.x] = idv;
    __syncthreads();
    for (int o = 128; o > 0; o >>= 1) {
        if (threadIdx.x < o) sh[threadIdx.x] += sh[threadIdx.x + o];
        __syncthreads();
    }
    if (threadIdx.x == 0) g_int[IOFF_PART + blockIdx.x] = sh[0];
}

__global__ void k_scan2() {
    __shared__ int sh[256];
    int t = threadIdx.x;
    sh[t] = (t < NB) ? g_int[IOFF_PART + t] : 0;
    __syncthreads();
    if (t == 0) {
        int run = 0;
        for (int b = 0; b < NB; b++) { int v = sh[b]; sh[b] = run; run += v; }
    }
    __syncthreads();
    if (t < NB) g_int[IOFF_PPRE + t] = sh[t];
}

__global__ void k_scan3() {
    __shared__ int sh[256];
    int t = threadIdx.x;
    int i = blockIdx.x * 256 + t;
    int v = (i < NN) ? g_int[IOFF_IDEG + i] : 0;
    sh[t] = v;
    __syncthreads();
    for (int o = 1; o < 256; o <<= 1) {
        int x = (t >= o) ? sh[t - o] : 0;
        __syncthreads();
        sh[t] += x;
        __syncthreads();
    }
    int excl = sh[t] - v + g_int[IOFF_PPRE + blockIdx.x];
    if (i < NN) {
        g_int[IOFF_ROWP + i] = excl;
        g_int[IOFF_CUR + i] = excl;
    }
    if (i == NN - 1) g_int[IOFF_ROWP + NN] = excl + v;
}

__global__ void k_fill(const int* __restrict__ src, const int* __restrict__ dst, int E) {
    int e = blockIdx.x * blockDim.x + threadIdx.x;
    if (e < E) {
        int pos = atomicAdd(&g_int[IOFF_CUR + dst[e]], 1);
        g_int[IOFF_CSR + pos] = src[e];
    }
}

// y1 = in_feat * norm_src
__global__ void k_scale_x(const float* __restrict__ x) {
    int t = blockIdx.x * blockDim.x + threadIdx.x;
    if (t >= NN * 16) return;
    int n = t >> 4;
    float s = g_work[OFF_NSRC + n];
    float4 v = __ldg((const float4*)x + t);
    v.x *= s; v.y *= s; v.z *= s; v.w *= s;
    ((float4*)(g_work + OFF_Y1))[t] = v;
}

// ---------------- gather aggregation ----------------
// C threads per dst node, thread c owns float4 chunk c. Unroll-4 for MLP.
// All scratch addressed via template offsets (device-side only).
// EPI: acc = acc*norm_dst[n] + bias[c]  written to harness pointer outp.
template <int C, int LOGC, int MOFF, int AOFF, bool EPI>
__global__ void k_gather(float4* __restrict__ outp, const float4* __restrict__ bias) {
    int t = blockIdx.x * blockDim.x + threadIdx.x;
    int n = t >> LOGC;
    if (n >= NN) return;
    int c = t & (C - 1);
    int beg = __ldg(&g_int[IOFF_ROWP + n]);
    int end = __ldg(&g_int[IOFF_ROWP + n + 1]);
    const float4* msg = (const float4*)(g_work + MOFF);

    float4 acc = make_float4(0.f, 0.f, 0.f, 0.f);
    int i = beg;
    for (; i + 3 < end; i += 4) {
        int s0 = __ldg(&g_int[IOFF_CSR + i]);
        int s1 = __ldg(&g_int[IOFF_CSR + i + 1]);
        int s2 = __ldg(&g_int[IOFF_CSR + i + 2]);
        int s3 = __ldg(&g_int[IOFF_CSR + i + 3]);
        float4 v0 = __ldg(msg + s0 * C + c);
        float4 v1 = __ldg(msg + s1 * C + c);
        float4 v2 = __ldg(msg + s2 * C + c);
        float4 v3 = __ldg(msg + s3 * C + c);
        acc.x += (v0.x + v1.x) + (v2.x + v3.x);
        acc.y += (v0.y + v1.y) + (v2.y + v3.y);
        acc.z += (v0.z + v1.z) + (v2.z + v3.z);
        acc.w += (v0.w + v1.w) + (v2.w + v3.w);
    }
    for (; i < end; i++) {
        int s0 = __ldg(&g_int[IOFF_CSR + i]);
        float4 v0 = __ldg(msg + s0 * C + c);
        acc.x += v0.x; acc.y += v0.y; acc.z += v0.z; acc.w += v0.w;
    }
    if (EPI) {
        float nd = __ldg(&g_work[OFF_NDST + n]);
        float4 bb = __ldg(bias + c);
        acc.x = acc.x * nd + bb.x;
        acc.y = acc.y * nd + bb.y;
        acc.z = acc.z * nd + bb.z;
        acc.w = acc.w * nd + bb.w;
        outp[n * C + c] = acc;
    } else {
        ((float4*)(g_work + AOFF))[n * C + c] = acc;
    }
}

// ---------------- dense layers ----------------
template <int DIN, int DOUT, bool RELU, bool BIAS, bool SCALE_IN, bool SCALE_OUT,
          int INOFF, int OUTOFF>
__global__ void k_mm(const float* __restrict__ W, const float* __restrict__ b) {
    constexpr int JC = DOUT / 16;
    __shared__ float sW[DIN * DOUT];
    __shared__ float sb[DOUT];
    for (int i = threadIdx.x; i < DIN * DOUT; i += blockDim.x) sW[i] = W[i];
    if (BIAS) for (int i = threadIdx.x; i < DOUT; i += blockDim.x) sb[i] = b[i];
    __syncthreads();

    int t = blockIdx.x * blockDim.x + threadIdx.x;
    int n = t / JC;
    int jc = t % JC;
    if (n >= NN) return;

    const float* in = g_work + INOFF + n * DIN;
    float si = SCALE_IN ? g_work[OFF_NDST + n] : 1.0f;

    float acc[16];
#pragma unroll
    for (int j = 0; j < 16; j++) acc[j] = 0.0f;
#pragma unroll
    for (int k = 0; k < DIN; k += 4) {
        float4 v = __ldg((const float4*)(in + k));
        float vv[4] = {v.x * si, v.y * si, v.z * si, v.w * si};
#pragma unroll
        for (int kk = 0; kk < 4; kk++) {
#pragma unroll
            for (int j = 0; j < 16; j++)
                acc[j] += vv[kk] * sW[(k + kk) * DOUT + jc * 16 + j];
        }
    }
    float so = SCALE_OUT ? g_work[OFF_NSRC + n] : 1.0f;
    float4* o = (float4*)(g_work + OUTOFF + n * DOUT + jc * 16);
#pragma unroll
    for (int j4 = 0; j4 < 4; j4++) {
        float r[4];
#pragma unroll
        for (int k = 0; k < 4; k++) {
            float x = acc[j4 * 4 + k];
            if (BIAS) x += sb[jc * 16 + j4 * 4 + k];
            if (RELU) x = fmaxf(x, 0.0f);
            r[k] = x * so;
        }
        o[j4] = make_float4(r[0], r[1], r[2], r[3]);
    }
}

// fused: embed = agg2*norm_dst + b2 -> d_out; p3 = (relu(embed) @ W3) * norm_src
__global__ void k_embed_p3(const float* __restrict__ W3, const float* __restrict__ b2,
                           float* __restrict__ out_embed) {
    __shared__ float sW[32 * 16];
    __shared__ float sb[32];
    for (int i = threadIdx.x; i < 512; i += blockDim.x) sW[i] = W3[i];
    if (threadIdx.x < 32) sb[threadIdx.x] = b2[threadIdx.x];
    __syncthreads();

    int n = blockIdx.x * blockDim.x + threadIdx.x;
    if (n >= NN) return;

    float nd = g_work[OFF_NDST + n];
    float ns = g_work[OFF_NSRC + n];

    float tr[32];
    const float4* row = (const float4*)(g_work + OFF_AGG2) + n * 8;
    float4* eo = (float4*)out_embed + n * 8;
#pragma unroll
    for (int c = 0; c < 8; c++) {
        float4 v = __ldg(row + c);
        v.x = v.x * nd + sb[c * 4 + 0];
        v.y = v.y * nd + sb[c * 4 + 1];
        v.z = v.z * nd + sb[c * 4 + 2];
        v.w = v.w * nd + sb[c * 4 + 3];
        eo[c] = v;
        tr[c * 4 + 0] = fmaxf(v.x, 0.0f);
        tr[c * 4 + 1] = fmaxf(v.y, 0.0f);
        tr[c * 4 + 2] = fmaxf(v.z, 0.0f);
        tr[c * 4 + 3] = fmaxf(v.w, 0.0f);
    }

    float acc[16];
#pragma unroll
    for (int j = 0; j < 16; j++) acc[j] = 0.0f;
#pragma unroll
    for (int k = 0; k < 32; k++) {
#pragma unroll
        for (int j = 0; j < 16; j++) acc[j] += tr[k] * sW[k * 16 + j];
    }
    float4* po = (float4*)(g_work + OFF_P3) + n * 4;
#pragma unroll
    for (int c = 0; c < 4; c++) {
        po[c] = make_float4(acc[c * 4 + 0] * ns, acc[c * 4 + 1] * ns,
                            acc[c * 4 + 2] * ns, acc[c * 4 + 3] * ns);
    }
}

// ---------------- launch ----------------

extern "C" void kernel_launch(void* const* d_in, const int* in_sizes, int n_in,
                              void* d_out, int out_size) {
    const float* x  = (const float*)d_in[0];
    const float* W1 = (const float*)d_in[1];
    const float* b1 = (const float*)d_in[2];
    const float* W2 = (const float*)d_in[3];
    const float* b2 = (const float*)d_in[4];
    const float* W3 = (const float*)d_in[5];
    const float* b3 = (const float*)d_in[6];
    const int* src  = (const int*)d_in[7];
    const int* dst  = (const int*)d_in[8];
    float* out = (float*)d_out;
    int E = in_sizes[7];
    (void)n_in; (void)out_size;

    const int TB = 256;
    auto blk = [](long n, int tb) { return (int)((n + tb - 1) / tb); };

    // degrees + norms + CSR build
    k_zero_deg<<<blk(2 * NN, TB), TB>>>();
    k_deg<<<blk(E, TB), TB>>>(src, dst, E);
    k_norm_scan1<<<NB, 256>>>();
    k_scan2<<<1, 256>>>();
    k_scan3<<<NB, 256>>>();
    k_fill<<<blk(E, TB), TB>>>(src, dst, E);

    // layer 1
    k_scale_x<<<blk((long)NN * 16, TB), TB>>>(x);
    k_gather<16, 4, OFF_Y1, OFF_AGG1, false><<<blk((long)NN * 16, TB), TB>>>(nullptr, nullptr);
    k_mm<64, 64, true, true, true, false, OFF_AGG1, OFF_H1>
        <<<blk((long)NN * 4, TB), TB>>>(W1, b1);

    // layer 2
    k_mm<64, 32, false, false, false, true, OFF_H1, OFF_P2>
        <<<blk((long)NN * 2, TB), TB>>>(W2, nullptr);
    k_gather<8, 3, OFF_P2, OFF_AGG2, false><<<blk((long)NN * 8, TB), TB>>>(nullptr, nullptr);

    // embed -> out[0:32NN]; p3 = (relu(embed)@W3)*nsrc
    k_embed_p3<<<blk(NN, TB), TB>>>(W3, b2, out);

    // layer 3: gather + fused epilogue -> out[32NN:48NN]
    k_gather<4, 2, OFF_P3, 0, true><<<blk((long)NN * 4, TB), TB>>>(
        (float4*)(out + 32 * NN), (const float4*)b3);
}

// round 6
// speedup vs baseline: 1.0708x; 1.0708x over previous
#include <cuda_runtime.h>
#include <cuda_fp16.h>

#define NN 50000
#define NEMAX 1000000
#define NB 196          // ceil(NN/256)

// ---------------- scratch ----------------
// floats: [nsrc NN | ndst NN | agg1 64NN | h1 64NN | agg2 32NN]
__device__ __align__(256) float g_work[162 * NN];
// halves (messages): [y1 64NN | p2 32NN | p3 16NN]
__device__ __align__(256) __half g_half[112 * NN];
// ints: [ideg NN | odeg NN | rowptr NN+1 | cursor NN | part 256 | csr NEMAX]
__device__ __align__(256) int g_int[4 * NN + 1 + 256 + NEMAX];

#define OFF_NSRC 0
#define OFF_NDST (NN)
#define OFF_AGG1 (2 * NN)
#define OFF_H1   (66 * NN)
#define OFF_AGG2 (130 * NN)

#define HOFF_Y1 0
#define HOFF_P2 (64 * NN)
#define HOFF_P3 (96 * NN)

#define IOFF_IDEG 0
#define IOFF_ODEG (NN)
#define IOFF_ROWP (2 * NN)
#define IOFF_CUR  (3 * NN + 1)
#define IOFF_PART (4 * NN + 1)
#define IOFF_CSR  (4 * NN + 1 + 256)

// ---------------- degree / norm / CSR ----------------

__global__ void k_zero_deg() {
    int i = blockIdx.x * blockDim.x + threadIdx.x;
    if (i < 2 * NN) g_int[i] = 0;
}

__global__ void k_deg(const int* __restrict__ src, const int* __restrict__ dst, int E) {
    int e = (blockIdx.x * blockDim.x + threadIdx.x) * 4;
    if (e + 3 < E) {
        int4 s = __ldg((const int4*)(src + e));
        int4 d = __ldg((const int4*)(dst + e));
        atomicAdd(&g_int[IOFF_ODEG + s.x], 1);
        atomicAdd(&g_int[IOFF_ODEG + s.y], 1);
        atomicAdd(&g_int[IOFF_ODEG + s.z], 1);
        atomicAdd(&g_int[IOFF_ODEG + s.w], 1);
        atomicAdd(&g_int[IOFF_IDEG + d.x], 1);
        atomicAdd(&g_int[IOFF_IDEG + d.y], 1);
        atomicAdd(&g_int[IOFF_IDEG + d.z], 1);
        atomicAdd(&g_int[IOFF_IDEG + d.w], 1);
    } else {
        for (int i = e; i < E; i++) {
            atomicAdd(&g_int[IOFF_ODEG + __ldg(src + i)], 1);
            atomicAdd(&g_int[IOFF_IDEG + __ldg(dst + i)], 1);
        }
    }
}

// norms + per-block partial sums of in_deg
__global__ void k_norm_scan1() {
    __shared__ int sh[256];
    int i = blockIdx.x * 256 + threadIdx.x;
    int idv = 0;
    if (i < NN) {
        idv = g_int[IOFF_IDEG + i];
        int odv = g_int[IOFF_ODEG + i];
        g_work[OFF_NSRC + i] = rsqrtf(fmaxf((float)odv, 1.0f));
        g_work[OFF_NDST + i] = rsqrtf(fmaxf((float)idv, 1.0f));
    }
    sh[threadIdx.x] = idv;
    __syncthreads();
    for (int o = 128; o > 0; o >>= 1) {
        if (threadIdx.x < o) sh[threadIdx.x] += sh[threadIdx.x + o];
        __syncthreads();
    }
    if (threadIdx.x == 0) g_int[IOFF_PART + blockIdx.x] = sh[0];
}

// each block redundantly prefix-scans the 196 partials (no separate scan2 kernel)
__global__ void k_scan3() {
    __shared__ int sp[256];
    __shared__ int sh[256];
    int t = threadIdx.x;
    sp[t] = (t < NB) ? g_int[IOFF_PART + t] : 0;
    __syncthreads();
    for (int o = 1; o < 256; o <<= 1) {
        int v = (t >= o) ? sp[t - o] : 0;
        __syncthreads();
        sp[t] += v;
        __syncthreads();
    }
    int blockpre = (blockIdx.x == 0) ? 0 : sp[blockIdx.x - 1];

    int i = blockIdx.x * 256 + t;
    int v = (i < NN) ? g_int[IOFF_IDEG + i] : 0;
    sh[t] = v;
    __syncthreads();
    for (int o = 1; o < 256; o <<= 1) {
        int x = (t >= o) ? sh[t - o] : 0;
        __syncthreads();
        sh[t] += x;
        __syncthreads();
    }
    int excl = sh[t] - v + blockpre;
    if (i < NN) {
        g_int[IOFF_ROWP + i] = excl;
        g_int[IOFF_CUR + i] = excl;
    }
    if (i == NN - 1) g_int[IOFF_ROWP + NN] = excl + v;
}

__global__ void k_fill(const int* __restrict__ src, const int* __restrict__ dst, int E) {
    int e = (blockIdx.x * blockDim.x + threadIdx.x) * 4;
    if (e + 3 < E) {
        int4 s = __ldg((const int4*)(src + e));
        int4 d = __ldg((const int4*)(dst + e));
        g_int[IOFF_CSR + atomicAdd(&g_int[IOFF_CUR + d.x], 1)] = s.x;
        g_int[IOFF_CSR + atomicAdd(&g_int[IOFF_CUR + d.y], 1)] = s.y;
        g_int[IOFF_CSR + atomicAdd(&g_int[IOFF_CUR + d.z], 1)] = s.z;
        g_int[IOFF_CSR + atomicAdd(&g_int[IOFF_CUR + d.w], 1)] = s.w;
    } else {
        for (int i = e; i < E; i++) {
            int pos = atomicAdd(&g_int[IOFF_CUR + __ldg(dst + i)], 1);
            g_int[IOFF_CSR + pos] = __ldg(src + i);
        }
    }
}

// y1 = half(in_feat * norm_src); thread handles 8 floats -> one uint4 of halves
__global__ void k_scale_x(const float* __restrict__ x) {
    int t = blockIdx.x * blockDim.x + threadIdx.x;
    if (t >= NN * 8) return;
    int n = t >> 3;
    int c = t & 7;
    float s = g_work[OFF_NSRC + n];
    const float4* px = (const float4*)(x + n * 64 + c * 8);
    float4 a = __ldg(px);
    float4 b = __ldg(px + 1);
    __half2 h0 = __floats2half2_rn(a.x * s, a.y * s);
    __half2 h1 = __floats2half2_rn(a.z * s, a.w * s);
    __half2 h2 = __floats2half2_rn(b.x * s, b.y * s);
    __half2 h3 = __floats2half2_rn(b.z * s, b.w * s);
    uint4 u;
    u.x = *(unsigned*)&h0; u.y = *(unsigned*)&h1;
    u.z = *(unsigned*)&h2; u.w = *(unsigned*)&h3;
    ((uint4*)(g_half + HOFF_Y1))[t] = u;
}

// ---------------- fp16 gather aggregation ----------------

__device__ __forceinline__ void add_h8(float acc[8], uint4 u) {
    float2 f;
    f = __half22float2(*reinterpret_cast<__half2*>(&u.x)); acc[0] += f.x; acc[1] += f.y;
    f = __half22float2(*reinterpret_cast<__half2*>(&u.y)); acc[2] += f.x; acc[3] += f.y;
    f = __half22float2(*reinterpret_cast<__half2*>(&u.z)); acc[4] += f.x; acc[5] += f.y;
    f = __half22float2(*reinterpret_cast<__half2*>(&u.w)); acc[6] += f.x; acc[7] += f.y;
}

// C uint4-chunks per node row (row = 8*C halves). Thread c owns chunk c (8 values).
// EPI: out = acc*norm_dst + bias chunk, written to harness pointer.
template <int C, int LOGC, int MOFF, int AOFF, bool EPI>
__global__ void k_gather_h(float4* __restrict__ outp, const float* __restrict__ bias) {
    int t = blockIdx.x * blockDim.x + threadIdx.x;
    int n = t >> LOGC;
    if (n >= NN) return;
    int c = t & (C - 1);
    int beg = __ldg(&g_int[IOFF_ROWP + n]);
    int end = __ldg(&g_int[IOFF_ROWP + n + 1]);
    const uint4* __restrict__ msg = (const uint4*)(g_half + MOFF);

    float acc[8];
#pragma unroll
    for (int j = 0; j < 8; j++) acc[j] = 0.0f;

    int i = beg;
    for (; i + 3 < end; i += 4) {
        int s0 = __ldg(&g_int[IOFF_CSR + i]);
        int s1 = __ldg(&g_int[IOFF_CSR + i + 1]);
        int s2 = __ldg(&g_int[IOFF_CSR + i + 2]);
        int s3 = __ldg(&g_int[IOFF_CSR + i + 3]);
        uint4 u0 = msg[s0 * C + c];
        uint4 u1 = msg[s1 * C + c];
        uint4 u2 = msg[s2 * C + c];
        uint4 u3 = msg[s3 * C + c];
        add_h8(acc, u0); add_h8(acc, u1); add_h8(acc, u2); add_h8(acc, u3);
    }
    for (; i < end; i++) {
        int s0 = __ldg(&g_int[IOFF_CSR + i]);
        add_h8(acc, msg[s0 * C + c]);
    }

    if (EPI) {
        float nd = __ldg(&g_work[OFF_NDST + n]);
        float4 b0 = __ldg((const float4*)(bias + c * 8));
        float4 b1 = __ldg((const float4*)(bias + c * 8) + 1);
        float4 r0 = make_float4(acc[0] * nd + b0.x, acc[1] * nd + b0.y,
                                acc[2] * nd + b0.z, acc[3] * nd + b0.w);
        float4 r1 = make_float4(acc[4] * nd + b1.x, acc[5] * nd + b1.y,
                                acc[6] * nd + b1.z, acc[7] * nd + b1.w);
        outp[(n * C + c) * 2] = r0;
        outp[(n * C + c) * 2 + 1] = r1;
    } else {
        float4* o = (float4*)(g_work + AOFF) + (n * C + c) * 2;
        o[0] = make_float4(acc[0], acc[1], acc[2], acc[3]);
        o[1] = make_float4(acc[4], acc[5], acc[6], acc[7]);
    }
}

// ---------------- dense layers ----------------
// out = f(scale_in * in) @ W (+b) (* scale_out); OUT_HALF writes fp16 to g_half.
template <int DIN, int DOUT, bool RELU, bool BIAS, bool SCALE_IN, bool SCALE_OUT,
          int INOFF, int OUTOFF, bool OUT_HALF>
__global__ void k_mm(const float* __restrict__ W, const float* __restrict__ b) {
    constexpr int JC = DOUT / 16;
    __shared__ float sW[DIN * DOUT];
    __shared__ float sb[DOUT];
    for (int i = threadIdx.x; i < DIN * DOUT; i += blockDim.x) sW[i] = W[i];
    if (BIAS) for (int i = threadIdx.x; i < DOUT; i += blockDim.x) sb[i] = b[i];
    __syncthreads();

    int t = blockIdx.x * blockDim.x + threadIdx.x;
    int n = t / JC;
    int jc = t % JC;
    if (n >= NN) return;

    const float* in = g_work + INOFF + n * DIN;
    float si = SCALE_IN ? g_work[OFF_NDST + n] : 1.0f;

    float acc[16];
#pragma unroll
    for (int j = 0; j < 16; j++) acc[j] = 0.0f;
#pragma unroll
    for (int k = 0; k < DIN; k += 4) {
        float4 v = __ldg((const float4*)(in + k));
        float vv[4] = {v.x * si, v.y * si, v.z * si, v.w * si};
#pragma unroll
        for (int kk = 0; kk < 4; kk++) {
#pragma unroll
            for (int j = 0; j < 16; j++)
                acc[j] += vv[kk] * sW[(k + kk) * DOUT + jc * 16 + j];
        }
    }
    float so = SCALE_OUT ? g_work[OFF_NSRC + n] : 1.0f;
    float r[16];
#pragma unroll
    for (int j = 0; j < 16; j++) {
        float v = acc[j];
        if (BIAS) v += sb[jc * 16 + j];
        if (RELU) v = fmaxf(v, 0.0f);
        r[j] = v * so;
    }
    if (OUT_HALF) {
        uint4 u[2];
#pragma unroll
        for (int q = 0; q < 2; q++) {
            __half2 h0 = __floats2half2_rn(r[q * 8 + 0], r[q * 8 + 1]);
            __half2 h1 = __floats2half2_rn(r[q * 8 + 2], r[q * 8 + 3]);
            __half2 h2 = __floats2half2_rn(r[q * 8 + 4], r[q * 8 + 5]);
            __half2 h3 = __floats2half2_rn(r[q * 8 + 6], r[q * 8 + 7]);
            u[q].x = *(unsigned*)&h0; u[q].y = *(unsigned*)&h1;
            u[q].z = *(unsigned*)&h2; u[q].w = *(unsigned*)&h3;
        }
        uint4* o = (uint4*)(g_half + OUTOFF + n * DOUT + jc * 16);
        o[0] = u[0]; o[1] = u[1];
    } else {
        float4* o = (float4*)(g_work + OUTOFF + n * DOUT + jc * 16);
#pragma unroll
        for (int j4 = 0; j4 < 4; j4++)
            o[j4] = make_float4(r[j4 * 4], r[j4 * 4 + 1], r[j4 * 4 + 2], r[j4 * 4 + 3]);
    }
}

// fused: embed = agg2*norm_dst + b2 -> d_out; p3 = half((relu(embed) @ W3) * norm_src)
__global__ void k_embed_p3(const float* __restrict__ W3, const float* __restrict__ b2,
                           float* __restrict__ out_embed) {
    __shared__ float sW[32 * 16];
    __shared__ float sb[32];
    for (int i = threadIdx.x; i < 512; i += blockDim.x) sW[i] = W3[i];
    if (threadIdx.x < 32) sb[threadIdx.x] = b2[threadIdx.x];
    __syncthreads();

    int n = blockIdx.x * blockDim.x + threadIdx.x;
    if (n >= NN) return;

    float nd = g_work[OFF_NDST + n];
    float ns = g_work[OFF_NSRC + n];

    float tr[32];
    const float4* row = (const float4*)(g_work + OFF_AGG2) + n * 8;
    float4* eo = (float4*)out_embed + n * 8;
#pragma unroll
    for (int c = 0; c < 8; c++) {
        float4 v = __ldg(row + c);
        v.x = v.x * nd + sb[c * 4 + 0];
        v.y = v.y * nd + sb[c * 4 + 1];
        v.z = v.z * nd + sb[c * 4 + 2];
        v.w = v.w * nd + sb[c * 4 + 3];
        eo[c] = v;
        tr[c * 4 + 0] = fmaxf(v.x, 0.0f);
        tr[c * 4 + 1] = fmaxf(v.y, 0.0f);
        tr[c * 4 + 2] = fmaxf(v.z, 0.0f);
        tr[c * 4 + 3] = fmaxf(v.w, 0.0f);
    }

    float acc[16];
#pragma unroll
    for (int j = 0; j < 16; j++) acc[j] = 0.0f;
#pragma unroll
    for (int k = 0; k < 32; k++) {
#pragma unroll
        for (int j = 0; j < 16; j++) acc[j] += tr[k] * sW[k * 16 + j];
    }

    uint4 u[2];
#pragma unroll
    for (int q = 0; q < 2; q++) {
        __half2 h0 = __floats2half2_rn(acc[q * 8 + 0] * ns, acc[q * 8 + 1] * ns);
        __half2 h1 = __floats2half2_rn(acc[q * 8 + 2] * ns, acc[q * 8 + 3] * ns);
        __half2 h2 = __floats2half2_rn(acc[q * 8 + 4] * ns, acc[q * 8 + 5] * ns);
        __half2 h3 = __floats2half2_rn(acc[q * 8 + 6] * ns, acc[q * 8 + 7] * ns);
        u[q].x = *(unsigned*)&h0; u[q].y = *(unsigned*)&h1;
        u[q].z = *(unsigned*)&h2; u[q].w = *(unsigned*)&h3;
    }
    uint4* po = (uint4*)(g_half + HOFF_P3 + n * 16);
    po[0] = u[0]; po[1] = u[1];
}

// ---------------- launch ----------------

extern "C" void kernel_launch(void* const* d_in, const int* in_sizes, int n_in,
                              void* d_out, int out_size) {
    const float* x  = (const float*)d_in[0];
    const float* W1 = (const float*)d_in[1];
    const float* b1 = (const float*)d_in[2];
    const float* W2 = (const float*)d_in[3];
    const float* b2 = (const float*)d_in[4];
    const float* W3 = (const float*)d_in[5];
    const float* b3 = (const float*)d_in[6];
    const int* src  = (const int*)d_in[7];
    const int* dst  = (const int*)d_in[8];
    float* out = (float*)d_out;
    int E = in_sizes[7];
    (void)n_in; (void)out_size;

    const int TB = 256;
    auto blk = [](long n, int tb) { return (int)((n + tb - 1) / tb); };

    // degrees + norms + CSR build
    k_zero_deg<<<blk(2 * NN, TB), TB>>>();
    k_deg<<<blk((E + 3) / 4, TB), TB>>>(src, dst, E);
    k_norm_scan1<<<NB, 256>>>();
    k_scan3<<<NB, 256>>>();
    k_fill<<<blk((E + 3) / 4, TB), TB>>>(src, dst, E);

    // layer 1: y1(half) -> gather(C=8) -> mm1
    k_scale_x<<<blk((long)NN * 8, TB), TB>>>(x);
    k_gather_h<8, 3, HOFF_Y1, OFF_AGG1, false><<<blk((long)NN * 8, TB), TB>>>(nullptr, nullptr);
    k_mm<64, 64, true, true, true, false, OFF_AGG1, OFF_H1, false>
        <<<blk((long)NN * 4, TB), TB>>>(W1, b1);

    // layer 2: p2(half) = (h1@W2)*nsrc -> gather(C=4)
    k_mm<64, 32, false, false, false, true, OFF_H1, HOFF_P2, true>
        <<<blk((long)NN * 2, TB), TB>>>(W2, nullptr);
    k_gather_h<4, 2, HOFF_P2, OFF_AGG2, false><<<blk((long)NN * 4, TB), TB>>>(nullptr, nullptr);

    // embed -> out[0:32NN]; p3(half) = (relu(embed)@W3)*nsrc
    k_embed_p3<<<blk(NN, TB), TB>>>(W3, b2, out);

    // layer 3: gather(C=2) + fused epilogue -> out[32NN:48NN]
    k_gather_h<2, 1, HOFF_P3, 0, true><<<blk((long)NN * 2, TB), TB>>>(
        (float4*)(out + 32 * NN), b3);
}

// round 7
// speedup vs baseline: 1.0836x; 1.0120x over previous
#include <cuda_runtime.h>
#include <cuda_fp16.h>

#define NN 50000
#define NEMAX 1000000
#define NB 196          // ceil(NN/256)

// ---------------- scratch ----------------
// floats: [nsrc NN | ndst NN]
__device__ __align__(256) float g_work[2 * NN];
// halves (messages): [y1 64NN | p2 32NN | p3 16NN]
__device__ __align__(256) __half g_half[112 * NN];
// ints: [ideg NN | odeg NN | rowptr NN+1 | cursor NN | csr NEMAX]
__device__ __align__(256) int g_int[4 * NN + 1 + NEMAX];
// lookback scan state: bit32 = valid flag, low 32 = block aggregate (zero-init)
__device__ __align__(256) unsigned long long g_status[256];

#define OFF_NSRC 0
#define OFF_NDST (NN)

#define HOFF_Y1 0
#define HOFF_P2 (64 * NN)
#define HOFF_P3 (96 * NN)

#define IOFF_IDEG 0
#define IOFF_ODEG (NN)
#define IOFF_ROWP (2 * NN)
#define IOFF_CUR  (3 * NN + 1)
#define IOFF_CSR  (4 * NN + 1)

// ---------------- degree (counters zeroed by prev call's k_L3 / static init) ----

__global__ void k_deg(const int* __restrict__ src, const int* __restrict__ dst, int E) {
    int e = (blockIdx.x * blockDim.x + threadIdx.x) * 4;
    if (e + 3 < E) {
        int4 s = __ldg((const int4*)(src + e));
        int4 d = __ldg((const int4*)(dst + e));
        atomicAdd(&g_int[IOFF_ODEG + s.x], 1);
        atomicAdd(&g_int[IOFF_ODEG + s.y], 1);
        atomicAdd(&g_int[IOFF_ODEG + s.z], 1);
        atomicAdd(&g_int[IOFF_ODEG + s.w], 1);
        atomicAdd(&g_int[IOFF_IDEG + d.x], 1);
        atomicAdd(&g_int[IOFF_IDEG + d.y], 1);
        atomicAdd(&g_int[IOFF_IDEG + d.z], 1);
        atomicAdd(&g_int[IOFF_IDEG + d.w], 1);
    } else {
        for (int i = e; i < E; i++) {
            atomicAdd(&g_int[IOFF_ODEG + __ldg(src + i)], 1);
            atomicAdd(&g_int[IOFF_IDEG + __ldg(dst + i)], 1);
        }
    }
}

// ---------------- fused: norms + y1 scale + single-pass rowptr scan ------------

__global__ void k_scan_norm(const float* __restrict__ x) {
    __shared__ int sh[256];
    int t = threadIdx.x;
    int bid = blockIdx.x;
    int i = bid * 256 + t;

    int idv = 0, odv = 0;
    if (i < NN) {
        idv = g_int[IOFF_IDEG + i];
        odv = g_int[IOFF_ODEG + i];
    }
    float ns = rsqrtf(fmaxf((float)odv, 1.0f));
    float nd = rsqrtf(fmaxf((float)idv, 1.0f));
    if (i < NN) {
        g_work[OFF_NSRC + i] = ns;
        g_work[OFF_NDST + i] = nd;
    }

    // block-inclusive scan of in-degree
    sh[t] = idv;
    __syncthreads();
    for (int o = 1; o < 256; o <<= 1) {
        int v = (t >= o) ? sh[t - o] : 0;
        __syncthreads();
        sh[t] += v;
        __syncthreads();
    }
    int incl = sh[t];
    int total = sh[255];

    // publish this block's aggregate (packed flag|value, single-word atomic)
    if (t == 0)
        atomicExch(&g_status[bid], (1ULL << 32) | (unsigned long long)(unsigned)total);

    // y1 = half(x_row * nsrc) — bulk work here hides the lookback wait
    if (i < NN) {
        const float4* px = (const float4*)(x + (long)i * 64);
        uint4* py = (uint4*)(g_half + HOFF_Y1) + i * 8;
#pragma unroll
        for (int q = 0; q < 8; q++) {
            float4 a = __ldg(px + q * 2);
            float4 b = __ldg(px + q * 2 + 1);
            __half2 h0 = __floats2half2_rn(a.x * ns, a.y * ns);
            __half2 h1 = __floats2half2_rn(a.z * ns, a.w * ns);
            __half2 h2 = __floats2half2_rn(b.x * ns, b.y * ns);
            __half2 h3 = __floats2half2_rn(b.z * ns, b.w * ns);
            uint4 u;
            u.x = *(unsigned*)&h0; u.y = *(unsigned*)&h1;
            u.z = *(unsigned*)&h2; u.w = *(unsigned*)&h3;
            py[q] = u;
        }
    }

    // parallel lookback: thread t spins on block t's aggregate (t < bid)
    int myagg = 0;
    if (t < bid) {
        unsigned long long v;
        do { v = atomicOr(&g_status[t], 0ULL); } while ((v >> 32) == 0);
        myagg = (int)(v & 0xffffffffULL);
    }
    __syncthreads();
    sh[t] = myagg;
    __syncthreads();
    for (int o = 128; o > 0; o >>= 1) {
        if (t < o) sh[t] += sh[t + o];
        __syncthreads();
    }
    int blockpre = sh[0];

    int excl = blockpre + incl - idv;
    if (i < NN) {
        g_int[IOFF_ROWP + i] = excl;
        g_int[IOFF_CUR + i] = excl;
    }
    if (i == NN - 1) g_int[IOFF_ROWP + NN] = excl + idv;
}

__global__ void k_fill(const int* __restrict__ src, const int* __restrict__ dst, int E) {
    int e = (blockIdx.x * blockDim.x + threadIdx.x) * 4;
    if (e + 3 < E) {
        int4 s = __ldg((const int4*)(src + e));
        int4 d = __ldg((const int4*)(dst + e));
        g_int[IOFF_CSR + atomicAdd(&g_int[IOFF_CUR + d.x], 1)] = s.x;
        g_int[IOFF_CSR + atomicAdd(&g_int[IOFF_CUR + d.y], 1)] = s.y;
        g_int[IOFF_CSR + atomicAdd(&g_int[IOFF_CUR + d.z], 1)] = s.z;
        g_int[IOFF_CSR + atomicAdd(&g_int[IOFF_CUR + d.w], 1)] = s.w;
    } else {
        for (int i = e; i < E; i++) {
            int pos = atomicAdd(&g_int[IOFF_CUR + __ldg(dst + i)], 1);
            g_int[IOFF_CSR + pos] = __ldg(src + i);
        }
    }
}

// ---------------- fp16 gather helper ----------------

__device__ __forceinline__ void add_h8(float acc[8], uint4 u) {
    float2 f;
    f = __half22float2(*reinterpret_cast<__half2*>(&u.x)); acc[0] += f.x; acc[1] += f.y;
    f = __half22float2(*reinterpret_cast<__half2*>(&u.y)); acc[2] += f.x; acc[3] += f.y;
    f = __half22float2(*reinterpret_cast<__half2*>(&u.z)); acc[4] += f.x; acc[5] += f.y;
    f = __half22float2(*reinterpret_cast<__half2*>(&u.w)); acc[6] += f.x; acc[7] += f.y;
}

template <int C>
__device__ __forceinline__ void gather_row(float acc[8], int n, int c, const uint4* msg) {
    int beg = __ldg(&g_int[IOFF_ROWP + n]);
    int end = __ldg(&g_int[IOFF_ROWP + n + 1]);
    int i = beg;
    for (; i + 3 < end; i += 4) {
        int s0 = __ldg(&g_int[IOFF_CSR + i]);
        int s1 = __ldg(&g_int[IOFF_CSR + i + 1]);
        int s2 = __ldg(&g_int[IOFF_CSR + i + 2]);
        int s3 = __ldg(&g_int[IOFF_CSR + i + 3]);
        uint4 u0 = msg[s0 * C + c];
        uint4 u1 = msg[s1 * C + c];
        uint4 u2 = msg[s2 * C + c];
        uint4 u3 = msg[s3 * C + c];
        add_h8(acc, u0); add_h8(acc, u1); add_h8(acc, u2); add_h8(acc, u3);
    }
    for (; i < end; i++) {
        int s0 = __ldg(&g_int[IOFF_CSR + i]);
        add_h8(acc, msg[s0 * C + c]);
    }
}

// ---------------- fused layer 1: gather(y1) -> h1 -> p2(fp16) ----------------
// 256 thr = 32 nodes x 8 chunks. agg1/h1 live only in smem.

__global__ void k_L1(const float* __restrict__ W1, const float* __restrict__ b1,
                     const float* __restrict__ W2) {
    __shared__ float sW1[64 * 64];
    __shared__ float sW2[64 * 32];
    __shared__ float sb1[64];
    __shared__ float sagg[32][68];
    __shared__ float sh1[32][68];

    int t = threadIdx.x;
    for (int i = t; i < 64 * 64; i += 256) sW1[i] = W1[i];
    for (int i = t; i < 64 * 32; i += 256) sW2[i] = W2[i];
    if (t < 64) sb1[t] = b1[t];

    int ln = t >> 3;            // local node 0..31
    int c = t & 7;              // chunk 0..7 (8 halves each)
    int node = blockIdx.x * 32 + ln;
    bool valid = node < NN;

    float acc[8];
#pragma unroll
    for (int j = 0; j < 8; j++) acc[j] = 0.0f;
    float nd = 0.0f, ns = 0.0f;
    if (valid) {
        gather_row<8>(acc, node, c, (const uint4*)(g_half + HOFF_Y1));
        nd = __ldg(&g_work[OFF_NDST + node]);
        ns = __ldg(&g_work[OFF_NSRC + node]);
    }
#pragma unroll
    for (int j = 0; j < 8; j++) sagg[ln][c * 8 + j] = acc[j] * nd;
    __syncthreads();

    // h1[c*8+jj] = relu(sum_k sagg[k] * W1[k][c*8+jj] + b1)
    float h[8];
#pragma unroll
    for (int j = 0; j < 8; j++) h[j] = sb1[c * 8 + j];
#pragma unroll 4
    for (int k = 0; k < 64; k++) {
        float a = sagg[ln][k];
        float4 w0 = *(const float4*)&sW1[k * 64 + c * 8];
        float4 w1 = *(const float4*)&sW1[k * 64 + c * 8 + 4];
        h[0] += a * w0.x; h[1] += a * w0.y; h[2] += a * w0.z; h[3] += a * w0.w;
        h[4] += a * w1.x; h[5] += a * w1.y; h[6] += a * w1.z; h[7] += a * w1.w;
    }
#pragma unroll
    for (int j = 0; j < 8; j++) sh1[ln][c * 8 + j] = fmaxf(h[j], 0.0f);
    __syncthreads();

    // p2[c*4+jj] = (sum_k h1[k] * W2[k][c*4+jj]) * nsrc  -> fp16
    float p[4] = {0.f, 0.f, 0.f, 0.f};
#pragma unroll 4
    for (int k = 0; k < 64; k++) {
        float a = sh1[ln][k];
        float4 w = *(const float4*)&sW2[k * 32 + c * 4];
        p[0] += a * w.x; p[1] += a * w.y; p[2] += a * w.z; p[3] += a * w.w;
    }
    if (valid) {
        __half2 h0 = __floats2half2_rn(p[0] * ns, p[1] * ns);
        __half2 h1v = __floats2half2_rn(p[2] * ns, p[3] * ns);
        uint2 u;
        u.x = *(unsigned*)&h0; u.y = *(unsigned*)&h1v;
        ((uint2*)(g_half + HOFF_P2))[node * 8 + c] = u;
    }
}

// ---------------- fused layer 2: gather(p2) -> embed(out) -> p3(fp16) --------
// 256 thr = 64 nodes x 4 chunks.

__global__ void k_L2(const float* __restrict__ W3, const float* __restrict__ b2,
                     float* __restrict__ out_embed) {
    __shared__ float sW3[32 * 16];
    __shared__ float sb2[32];
    __shared__ float semb[64][36];

    int t = threadIdx.x;
    for (int i = t; i < 32 * 16; i += 256) sW3[i] = W3[i];
    if (t < 32) sb2[t] = b2[t];

    int ln = t >> 2;            // local node 0..63
    int c = t & 3;              // chunk 0..3
    int node = blockIdx.x * 64 + ln;
    bool valid = node < NN;

    float acc[8];
#pragma unroll
    for (int j = 0; j < 8; j++) acc[j] = 0.0f;
    float nd = 0.0f, ns = 0.0f;
    if (valid) {
        gather_row<4>(acc, node, c, (const uint4*)(g_half + HOFF_P2));
        nd = __ldg(&g_work[OFF_NDST + node]);
        ns = __ldg(&g_work[OFF_NSRC + node]);
    }
    // embed = acc*nd + b2 -> gmem out; relu -> smem
    float e[8];
#pragma unroll
    for (int j = 0; j < 8; j++) {
        e[j] = acc[j] * nd + sb2[c * 8 + j];
        semb[ln][c * 8 + j] = fmaxf(e[j], 0.0f);
    }
    if (valid) {
        float4* eo = (float4*)(out_embed + (long)node * 32 + c * 8);
        eo[0] = make_float4(e[0], e[1], e[2], e[3]);
        eo[1] = make_float4(e[4], e[5], e[6], e[7]);
    }
    __syncthreads();

    // p3[c*4+jj] = (sum_k relu(embed)[k] * W3[k][c*4+jj]) * nsrc -> fp16
    float p[4] = {0.f, 0.f, 0.f, 0.f};
#pragma unroll 4
    for (int k = 0; k < 32; k++) {
        float a = semb[ln][k];
        float4 w = *(const float4*)&sW3[k * 16 + c * 4];
        p[0] += a * w.x; p[1] += a * w.y; p[2] += a * w.z; p[3] += a * w.w;
    }
    if (valid) {
        __half2 h0 = __floats2half2_rn(p[0] * ns, p[1] * ns);
        __half2 h1v = __floats2half2_rn(p[2] * ns, p[3] * ns);
        uint2 u;
        u.x = *(unsigned*)&h0; u.y = *(unsigned*)&h1v;
        ((uint2*)(g_half + HOFF_P3))[node * 4 + c] = u;
    }
}

// ---------------- layer 3: gather(p3) + epilogue + reset state for next call --

__global__ void k_L3(const float* __restrict__ b3, float* __restrict__ out_h) {
    int t = blockIdx.x * blockDim.x + threadIdx.x;
    int n = t >> 1;
    int c = t & 1;
    if (n < NN) {
        float acc[8];
#pragma unroll
        for (int j = 0; j < 8; j++) acc[j] = 0.0f;
        gather_row<2>(acc, n, c, (const uint4*)(g_half + HOFF_P3));
        float nd = __ldg(&g_work[OFF_NDST + n]);
        float4 b0 = __ldg((const float4*)b3 + c * 2);
        float4 b1v = __ldg((const float4*)b3 + c * 2 + 1);
        float4* o = (float4*)(out_h + (long)n * 16 + c * 8);
        o[0] = make_float4(acc[0] * nd + b0.x, acc[1] * nd + b0.y,
                           acc[2] * nd + b0.z, acc[3] * nd + b0.w);
        o[1] = make_float4(acc[4] * nd + b1v.x, acc[5] * nd + b1v.y,
                           acc[6] * nd + b1v.z, acc[7] * nd + b1v.w);
    }
    // reset degree counters + scan flags for the next call
    if (t < 2 * NN) g_int[t] = 0;
    if (t < 256) g_status[t] = 0ULL;
}

// ---------------- launch ----------------

extern "C" void kernel_launch(void* const* d_in, const int* in_sizes, int n_in,
                              void* d_out, int out_size) {
    const float* x  = (const float*)d_in[0];
    const float* W1 = (const float*)d_in[1];
    const float* b1 = (const float*)d_in[2];
    const float* W2 = (const float*)d_in[3];
    const float* b2 = (const float*)d_in[4];
    const float* W3 = (const float*)d_in[5];
    const float* b3 = (const float*)d_in[6];
    const int* src  = (const int*)d_in[7];
    const int* dst  = (const int*)d_in[8];
    float* out = (float*)d_out;
    int E = in_sizes[7];
    (void)n_in; (void)out_size;

    const int TB = 256;
    auto blk = [](long n, int tb) { return (int)((n + tb - 1) / tb); };

    k_deg<<<blk((E + 3) / 4, TB), TB>>>(src, dst, E);
    k_scan_norm<<<NB, 256>>>(x);
    k_fill<<<blk((E + 3) / 4, TB), TB>>>(src, dst, E);
    k_L1<<<blk(NN, 32), 256>>>(W1, b1, W2);
    k_L2<<<blk(NN, 64), 256>>>(W3, b2, out);
    k_L3<<<blk((long)NN * 2, TB), TB>>>(b3, out + 32 * NN);
}

// round 8
// speedup vs baseline: 1.0849x; 1.0012x over previous
#include <cuda_runtime.h>
#include <cuda_fp16.h>

#define NN 50000
#define NEMAX 1000000
#define NB 196          // ceil(NN/256)

// ---------------- scratch ----------------
__device__ __align__(256) float g_work[2 * NN];                 // [nsrc | ndst]
__device__ __align__(256) __half g_half[112 * NN];              // [y1 64NN | p2 32NN | p3 16NN]
__device__ __align__(256) int g_int[4 * NN + 1 + NEMAX];        // [ideg|odeg|rowp|cur|csr]
__device__ __align__(256) unsigned long long g_status[256];     // lookback state (zero-init)

#define OFF_NSRC 0
#define OFF_NDST (NN)

#define HOFF_Y1 0
#define HOFF_P2 (64 * NN)
#define HOFF_P3 (96 * NN)

#define IOFF_IDEG 0
#define IOFF_ODEG (NN)
#define IOFF_ROWP (2 * NN)
#define IOFF_CUR  (3 * NN + 1)
#define IOFF_CSR  (4 * NN + 1)

// ---------------- degree (counters zeroed by prev call's k_L3 / static init) ----

__global__ void k_deg(const int* __restrict__ src, const int* __restrict__ dst, int E) {
    int e = (blockIdx.x * blockDim.x + threadIdx.x) * 4;
    if (e + 3 < E) {
        int4 s = __ldg((const int4*)(src + e));
        int4 d = __ldg((const int4*)(dst + e));
        atomicAdd(&g_int[IOFF_ODEG + s.x], 1);
        atomicAdd(&g_int[IOFF_ODEG + s.y], 1);
        atomicAdd(&g_int[IOFF_ODEG + s.z], 1);
        atomicAdd(&g_int[IOFF_ODEG + s.w], 1);
        atomicAdd(&g_int[IOFF_IDEG + d.x], 1);
        atomicAdd(&g_int[IOFF_IDEG + d.y], 1);
        atomicAdd(&g_int[IOFF_IDEG + d.z], 1);
        atomicAdd(&g_int[IOFF_IDEG + d.w], 1);
    } else {
        for (int i = e; i < E; i++) {
            atomicAdd(&g_int[IOFF_ODEG + __ldg(src + i)], 1);
            atomicAdd(&g_int[IOFF_IDEG + __ldg(dst + i)], 1);
        }
    }
}

// ---------------- fused: norms + y1 scale + single-pass rowptr scan ------------

__global__ void k_scan_norm(const float* __restrict__ x) {
    __shared__ int sh[256];
    int t = threadIdx.x;
    int bid = blockIdx.x;
    int i = bid * 256 + t;

    int idv = 0, odv = 0;
    if (i < NN) {
        idv = g_int[IOFF_IDEG + i];
        odv = g_int[IOFF_ODEG + i];
    }
    float ns = rsqrtf(fmaxf((float)odv, 1.0f));
    float nd = rsqrtf(fmaxf((float)idv, 1.0f));
    if (i < NN) {
        g_work[OFF_NSRC + i] = ns;
        g_work[OFF_NDST + i] = nd;
    }

    sh[t] = idv;
    __syncthreads();
    for (int o = 1; o < 256; o <<= 1) {
        int v = (t >= o) ? sh[t - o] : 0;
        __syncthreads();
        sh[t] += v;
        __syncthreads();
    }
    int incl = sh[t];
    int total = sh[255];

    if (t == 0)
        atomicExch(&g_status[bid], (1ULL << 32) | (unsigned long long)(unsigned)total);

    // y1 = half(x_row * nsrc) — hides the lookback wait
    if (i < NN) {
        const float4* px = (const float4*)(x + (long)i * 64);
        uint4* py = (uint4*)(g_half + HOFF_Y1) + i * 8;
#pragma unroll
        for (int q = 0; q < 8; q++) {
            float4 a = __ldg(px + q * 2);
            float4 b = __ldg(px + q * 2 + 1);
            __half2 h0 = __floats2half2_rn(a.x * ns, a.y * ns);
            __half2 h1 = __floats2half2_rn(a.z * ns, a.w * ns);
            __half2 h2 = __floats2half2_rn(b.x * ns, b.y * ns);
            __half2 h3 = __floats2half2_rn(b.z * ns, b.w * ns);
            uint4 u;
            u.x = *(unsigned*)&h0; u.y = *(unsigned*)&h1;
            u.z = *(unsigned*)&h2; u.w = *(unsigned*)&h3;
            py[q] = u;
        }
    }

    int myagg = 0;
    if (t < bid) {
        unsigned long long v;
        do { v = atomicOr(&g_status[t], 0ULL); } while ((v >> 32) == 0);
        myagg = (int)(v & 0xffffffffULL);
    }
    __syncthreads();
    sh[t] = myagg;
    __syncthreads();
    for (int o = 128; o > 0; o >>= 1) {
        if (t < o) sh[t] += sh[t + o];
        __syncthreads();
    }
    int blockpre = sh[0];

    int excl = blockpre + incl - idv;
    if (i < NN) {
        g_int[IOFF_ROWP + i] = excl;
        g_int[IOFF_CUR + i] = excl;
    }
    if (i == NN - 1) g_int[IOFF_ROWP + NN] = excl + idv;
}

__global__ void k_fill(const int* __restrict__ src, const int* __restrict__ dst, int E) {
    int e = (blockIdx.x * blockDim.x + threadIdx.x) * 4;
    if (e + 3 < E) {
        int4 s = __ldg((const int4*)(src + e));
        int4 d = __ldg((const int4*)(dst + e));
        g_int[IOFF_CSR + atomicAdd(&g_int[IOFF_CUR + d.x], 1)] = s.x;
        g_int[IOFF_CSR + atomicAdd(&g_int[IOFF_CUR + d.y], 1)] = s.y;
        g_int[IOFF_CSR + atomicAdd(&g_int[IOFF_CUR + d.z], 1)] = s.z;
        g_int[IOFF_CSR + atomicAdd(&g_int[IOFF_CUR + d.w], 1)] = s.w;
    } else {
        for (int i = e; i < E; i++) {
            int pos = atomicAdd(&g_int[IOFF_CUR + __ldg(dst + i)], 1);
            g_int[IOFF_CSR + pos] = __ldg(src + i);
        }
    }
}

// ---------------- packed fp32x2 accumulation helpers ----------------

__device__ __forceinline__ void acc_h2(unsigned long long& a, __half2 h) {
    float2 f = __half22float2(h);
    unsigned long long p;
    asm("mov.b64 %0, {%1, %2};" : "=l"(p) : "f"(f.x), "f"(f.y));
    asm("add.rn.f32x2 %0, %0, %1;" : "+l"(a) : "l"(p));
}

// accumulate two edges' chunks: fp16 pairwise pre-sum (depth 1), then packed f32x2
__device__ __forceinline__ void acc_pair(unsigned long long acc[4], uint4 a, uint4 b) {
    __half2 s0 = __hadd2(*(__half2*)&a.x, *(__half2*)&b.x);
    __half2 s1 = __hadd2(*(__half2*)&a.y, *(__half2*)&b.y);
    __half2 s2 = __hadd2(*(__half2*)&a.z, *(__half2*)&b.z);
    __half2 s3 = __hadd2(*(__half2*)&a.w, *(__half2*)&b.w);
    acc_h2(acc[0], s0); acc_h2(acc[1], s1); acc_h2(acc[2], s2); acc_h2(acc[3], s3);
}

__device__ __forceinline__ void acc_one(unsigned long long acc[4], uint4 u) {
    acc_h2(acc[0], *(__half2*)&u.x);
    acc_h2(acc[1], *(__half2*)&u.y);
    acc_h2(acc[2], *(__half2*)&u.z);
    acc_h2(acc[3], *(__half2*)&u.w);
}

__device__ __forceinline__ void unpack8(const unsigned long long acc[4], float o[8]) {
#pragma unroll
    for (int k = 0; k < 4; k++)
        asm("mov.b64 {%0, %1}, %2;" : "=f"(o[2 * k]), "=f"(o[2 * k + 1]) : "l"(acc[k]));
}

// gather: C lanes per node (C | 32); idx loads shared via shfl within the lane group.
// Each iteration processes C edges with one idx LDG per thread.
template <int C>
__device__ __forceinline__ void gather_row(unsigned long long acc[4], int n, int c,
                                           const uint4* __restrict__ msg) {
    int beg = __ldg(&g_int[IOFF_ROWP + n]);
    int end = __ldg(&g_int[IOFF_ROWP + n + 1]);
    int lane = threadIdx.x & 31;
    unsigned gmask = ((C == 32) ? 0xFFFFFFFFu : ((1u << C) - 1u) << (lane & ~(C - 1)));

    int i = beg;
    for (; i + C - 1 < end; i += C) {
        int myidx = __ldg(&g_int[IOFF_CSR + i + c]);
#pragma unroll
        for (int k = 0; k < C; k += 2) {
            int s0 = __shfl_sync(gmask, myidx, k, C);
            int s1 = __shfl_sync(gmask, myidx, k + 1, C);
            uint4 u0 = msg[s0 * C + c];
            uint4 u1 = msg[s1 * C + c];
            acc_pair(acc, u0, u1);
        }
    }
    for (; i + 1 < end; i += 2) {
        int s0 = __ldg(&g_int[IOFF_CSR + i]);
        int s1 = __ldg(&g_int[IOFF_CSR + i + 1]);
        acc_pair(acc, msg[s0 * C + c], msg[s1 * C + c]);
    }
    if (i < end) {
        int s0 = __ldg(&g_int[IOFF_CSR + i]);
        acc_one(acc, msg[s0 * C + c]);
    }
}

// ---------------- fused layer 1: gather(y1) -> h1 -> p2(fp16) ----------------
// 256 thr = 32 nodes x 8 chunks. agg1/h1 share one smem buffer.

__global__ void k_L1(const float* __restrict__ W1, const float* __restrict__ b1,
                     const float* __restrict__ W2) {
    __shared__ float sW1[64 * 64];
    __shared__ float sW2[64 * 32];
    __shared__ float sb1[64];
    __shared__ float sbuf[32][68];   // agg1, then reused for relu(h1)

    int t = threadIdx.x;
    for (int i = t; i < 64 * 64; i += 256) sW1[i] = W1[i];
    for (int i = t; i < 64 * 32; i += 256) sW2[i] = W2[i];
    if (t < 64) sb1[t] = b1[t];

    int ln = t >> 3;
    int c = t & 7;
    int node = blockIdx.x * 32 + ln;
    bool valid = node < NN;

    unsigned long long acc64[4] = {0ULL, 0ULL, 0ULL, 0ULL};
    float nd = 0.0f, ns = 0.0f;
    if (valid) {
        gather_row<8>(acc64, node, c, (const uint4*)(g_half + HOFF_Y1));
        nd = __ldg(&g_work[OFF_NDST + node]);
        ns = __ldg(&g_work[OFF_NSRC + node]);
    }
    float acc[8];
    unpack8(acc64, acc);
#pragma unroll
    for (int j = 0; j < 8; j++) sbuf[ln][c * 8 + j] = acc[j] * nd;
    __syncthreads();

    // h1 = relu(agg1 @ W1 + b1) into regs
    float h[8];
#pragma unroll
    for (int j = 0; j < 8; j++) h[j] = sb1[c * 8 + j];
#pragma unroll 4
    for (int k = 0; k < 64; k++) {
        float a = sbuf[ln][k];
        float4 w0 = *(const float4*)&sW1[k * 64 + c * 8];
        float4 w1 = *(const float4*)&sW1[k * 64 + c * 8 + 4];
        h[0] += a * w0.x; h[1] += a * w0.y; h[2] += a * w0.z; h[3] += a * w0.w;
        h[4] += a * w1.x; h[5] += a * w1.y; h[6] += a * w1.z; h[7] += a * w1.w;
    }
    __syncthreads();   // all reads of agg1 done -> reuse buffer
#pragma unroll
    for (int j = 0; j < 8; j++) sbuf[ln][c * 8 + j] = fmaxf(h[j], 0.0f);
    __syncthreads();

    // p2 = (h1 @ W2) * nsrc -> fp16
    float p[4] = {0.f, 0.f, 0.f, 0.f};
#pragma unroll 4
    for (int k = 0; k < 64; k++) {
        float a = sbuf[ln][k];
        float4 w = *(const float4*)&sW2[k * 32 + c * 4];
        p[0] += a * w.x; p[1] += a * w.y; p[2] += a * w.z; p[3] += a * w.w;
    }
    if (valid) {
        __half2 h0 = __floats2half2_rn(p[0] * ns, p[1] * ns);
        __half2 h1v = __floats2half2_rn(p[2] * ns, p[3] * ns);
        uint2 u;
        u.x = *(unsigned*)&h0; u.y = *(unsigned*)&h1v;
        ((uint2*)(g_half + HOFF_P2))[node * 8 + c] = u;
    }
}

// ---------------- fused layer 2: gather(p2) -> embed(out) -> p3(fp16) --------
// 256 thr = 64 nodes x 4 chunks.

__global__ void k_L2(const float* __restrict__ W3, const float* __restrict__ b2,
                     float* __restrict__ out_embed) {
    __shared__ float sW3[32 * 16];
    __shared__ float sb2[32];
    __shared__ float semb[64][36];

    int t = threadIdx.x;
    for (int i = t; i < 32 * 16; i += 256) sW3[i] = W3[i];
    if (t < 32) sb2[t] = b2[t];

    int ln = t >> 2;
    int c = t & 3;
    int node = blockIdx.x * 64 + ln;
    bool valid = node < NN;

    unsigned long long acc64[4] = {0ULL, 0ULL, 0ULL, 0ULL};
    float nd = 0.0f, ns = 0.0f;
    if (valid) {
        gather_row<4>(acc64, node, c, (const uint4*)(g_half + HOFF_P2));
        nd = __ldg(&g_work[OFF_NDST + node]);
        ns = __ldg(&g_work[OFF_NSRC + node]);
    }
    float acc[8];
    unpack8(acc64, acc);

    float e[8];
#pragma unroll
    for (int j = 0; j < 8; j++) {
        e[j] = acc[j] * nd + sb2[c * 8 + j];
        semb[ln][c * 8 + j] = fmaxf(e[j], 0.0f);
    }
    if (valid) {
        float4* eo = (float4*)(out_embed + (long)node * 32 + c * 8);
        eo[0] = make_float4(e[0], e[1], e[2], e[3]);
        eo[1] = make_float4(e[4], e[5], e[6], e[7]);
    }
    __syncthreads();

    float p[4] = {0.f, 0.f, 0.f, 0.f};
#pragma unroll 4
    for (int k = 0; k < 32; k++) {
        float a = semb[ln][k];
        float4 w = *(const float4*)&sW3[k * 16 + c * 4];
        p[0] += a * w.x; p[1] += a * w.y; p[2] += a * w.z; p[3] += a * w.w;
    }
    if (valid) {
        __half2 h0 = __floats2half2_rn(p[0] * ns, p[1] * ns);
        __half2 h1v = __floats2half2_rn(p[2] * ns, p[3] * ns);
        uint2 u;
        u.x = *(unsigned*)&h0; u.y = *(unsigned*)&h1v;
        ((uint2*)(g_half + HOFF_P3))[node * 4 + c] = u;
    }
}

// ---------------- layer 3: gather(p3) + epilogue + reset state ----------------

__global__ void k_L3(const float* __restrict__ b3, float* __restrict__ out_h) {
    int t = blockIdx.x * blockDim.x + threadIdx.x;
    int n = t >> 1;
    int c = t & 1;
    if (n < NN) {
        unsigned long long acc64[4] = {0ULL, 0ULL, 0ULL, 0ULL};
        gather_row<2>(acc64, n, c, (const uint4*)(g_half + HOFF_P3));
        float acc[8];
        unpack8(acc64, acc);
        float nd = __ldg(&g_work[OFF_NDST + n]);
        float4 b0 = __ldg((const float4*)b3 + c * 2);
        float4 b1v = __ldg((const float4*)b3 + c * 2 + 1);
        float4* o = (float4*)(out_h + (long)n * 16 + c * 8);
        o[0] = make_float4(acc[0] * nd + b0.x, acc[1] * nd + b0.y,
                           acc[2] * nd + b0.z, acc[3] * nd + b0.w);
        o[1] = make_float4(acc[4] * nd + b1v.x, acc[5] * nd + b1v.y,
                           acc[6] * nd + b1v.z, acc[7] * nd + b1v.w);
    }
    // reset degree counters + scan flags for next call
    if (t < 2 * NN) g_int[t] = 0;
    if (t < 256) g_status[t] = 0ULL;
}

// ---------------- launch ----------------

extern "C" void kernel_launch(void* const* d_in, const int* in_sizes, int n_in,
                              void* d_out, int out_size) {
    const float* x  = (const float*)d_in[0];
    const float* W1 = (const float*)d_in[1];
    const float* b1 = (const float*)d_in[2];
    const float* W2 = (const float*)d_in[3];
    const float* b2 = (const float*)d_in[4];
    const float* W3 = (const float*)d_in[5];
    const float* b3 = (const float*)d_in[6];
    const int* src  = (const int*)d_in[7];
    const int* dst  = (const int*)d_in[8];
    float* out = (float*)d_out;
    int E = in_sizes[7];
    (void)n_in; (void)out_size;

    const int TB = 256;
    auto blk = [](long n, int tb) { return (int)((n + tb - 1) / tb); };

    k_deg<<<blk((E + 3) / 4, TB), TB>>>(src, dst, E);
    k_scan_norm<<<NB, 256>>>(x);
    k_fill<<<blk((E + 3) / 4, TB), TB>>>(src, dst, E);
    k_L1<<<blk(NN, 32), 256>>>(W1, b1, W2);
    k_L2<<<blk(NN, 64), 256>>>(W3, b2, out);
    k_L3<<<blk((long)NN * 2, TB), TB>>>(b3, out + 32 * NN);
}

// round 9
// speedup vs baseline: 1.2259x; 1.1299x over previous
#include <cuda_runtime.h>
#include <cuda_fp16.h>

#define NN 50000
#define NEMAX 1000000
#define NB 196          // ceil(NN/256)

// ---------------- scratch ----------------
__device__ __align__(256) float g_work[2 * NN];                 // [nsrc | ndst]
__device__ __align__(256) __half g_half[112 * NN];              // [y1 64NN | p2 32NN | p3 16NN]
// ints: [ideg NN | odeg NN | rowp NN+1 (+3 pad) | cur NN | csr NEMAX] ; csr 16B-aligned
__device__ __align__(256) int g_int[4 * NN + 4 + NEMAX];
__device__ __align__(256) unsigned long long g_status[256];     // lookback state (zero-init)

#define OFF_NSRC 0
#define OFF_NDST (NN)

#define HOFF_Y1 0
#define HOFF_P2 (64 * NN)
#define HOFF_P3 (96 * NN)

#define IOFF_IDEG 0
#define IOFF_ODEG (NN)
#define IOFF_ROWP (2 * NN)
#define IOFF_CUR  (3 * NN + 4)
#define IOFF_CSR  (4 * NN + 4)

// ---------------- degree (counters zeroed by prev call's k_L3 / static init) ----

__global__ void k_deg(const int* __restrict__ src, const int* __restrict__ dst, int E) {
    int e = (blockIdx.x * blockDim.x + threadIdx.x) * 4;
    if (e + 3 < E) {
        int4 s = __ldg((const int4*)(src + e));
        int4 d = __ldg((const int4*)(dst + e));
        atomicAdd(&g_int[IOFF_ODEG + s.x], 1);
        atomicAdd(&g_int[IOFF_ODEG + s.y], 1);
        atomicAdd(&g_int[IOFF_ODEG + s.z], 1);
        atomicAdd(&g_int[IOFF_ODEG + s.w], 1);
        atomicAdd(&g_int[IOFF_IDEG + d.x], 1);
        atomicAdd(&g_int[IOFF_IDEG + d.y], 1);
        atomicAdd(&g_int[IOFF_IDEG + d.z], 1);
        atomicAdd(&g_int[IOFF_IDEG + d.w], 1);
    } else {
        for (int i = e; i < E; i++) {
            atomicAdd(&g_int[IOFF_ODEG + __ldg(src + i)], 1);
            atomicAdd(&g_int[IOFF_IDEG + __ldg(dst + i)], 1);
        }
    }
}

// ---------------- fused: norms + y1 scale + single-pass rowptr scan ------------

__global__ void k_scan_norm(const float* __restrict__ x) {
    __shared__ int sh[256];
    int t = threadIdx.x;
    int bid = blockIdx.x;
    int i = bid * 256 + t;

    int idv = 0, odv = 0;
    if (i < NN) {
        idv = g_int[IOFF_IDEG + i];
        odv = g_int[IOFF_ODEG + i];
    }
    float ns = rsqrtf(fmaxf((float)odv, 1.0f));
    float nd = rsqrtf(fmaxf((float)idv, 1.0f));
    if (i < NN) {
        g_work[OFF_NSRC + i] = ns;
        g_work[OFF_NDST + i] = nd;
    }

    sh[t] = idv;
    __syncthreads();
    for (int o = 1; o < 256; o <<= 1) {
        int v = (t >= o) ? sh[t - o] : 0;
        __syncthreads();
        sh[t] += v;
        __syncthreads();
    }
    int incl = sh[t];
    int total = sh[255];

    if (t == 0)
        atomicExch(&g_status[bid], (1ULL << 32) | (unsigned long long)(unsigned)total);

    // y1 = half(x_row * nsrc) — hides the lookback wait
    if (i < NN) {
        const float4* px = (const float4*)(x + (long)i * 64);
        uint4* py = (uint4*)(g_half + HOFF_Y1) + i * 8;
#pragma unroll
        for (int q = 0; q < 8; q++) {
            float4 a = __ldg(px + q * 2);
            float4 b = __ldg(px + q * 2 + 1);
            __half2 h0 = __floats2half2_rn(a.x * ns, a.y * ns);
            __half2 h1 = __floats2half2_rn(a.z * ns, a.w * ns);
            __half2 h2 = __floats2half2_rn(b.x * ns, b.y * ns);
            __half2 h3 = __floats2half2_rn(b.z * ns, b.w * ns);
            uint4 u;
            u.x = *(unsigned*)&h0; u.y = *(unsigned*)&h1;
            u.z = *(unsigned*)&h2; u.w = *(unsigned*)&h3;
            py[q] = u;
        }
    }

    int myagg = 0;
    if (t < bid) {
        unsigned long long v;
        do { v = atomicOr(&g_status[t], 0ULL); } while ((v >> 32) == 0);
        myagg = (int)(v & 0xffffffffULL);
    }
    __syncthreads();
    sh[t] = myagg;
    __syncthreads();
    for (int o = 128; o > 0; o >>= 1) {
        if (t < o) sh[t] += sh[t + o];
        __syncthreads();
    }
    int blockpre = sh[0];

    int excl = blockpre + incl - idv;
    if (i < NN) {
        g_int[IOFF_ROWP + i] = excl;
        g_int[IOFF_CUR + i] = excl;
    }
    if (i == NN - 1) g_int[IOFF_ROWP + NN] = excl + idv;
}

__global__ void k_fill(const int* __restrict__ src, const int* __restrict__ dst, int E) {
    int e = (blockIdx.x * blockDim.x + threadIdx.x) * 4;
    if (e + 3 < E) {
        int4 s = __ldg((const int4*)(src + e));
        int4 d = __ldg((const int4*)(dst + e));
        g_int[IOFF_CSR + atomicAdd(&g_int[IOFF_CUR + d.x], 1)] = s.x;
        g_int[IOFF_CSR + atomicAdd(&g_int[IOFF_CUR + d.y], 1)] = s.y;
        g_int[IOFF_CSR + atomicAdd(&g_int[IOFF_CUR + d.z], 1)] = s.z;
        g_int[IOFF_CSR + atomicAdd(&g_int[IOFF_CUR + d.w], 1)] = s.w;
    } else {
        for (int i = e; i < E; i++) {
            int pos = atomicAdd(&g_int[IOFF_CUR + __ldg(dst + i)], 1);
            g_int[IOFF_CSR + pos] = __ldg(src + i);
        }
    }
}

// ---------------- packed fp32x2 accumulation helpers ----------------

__device__ __forceinline__ void acc_h2(unsigned long long& a, __half2 h) {
    float2 f = __half22float2(h);
    unsigned long long p;
    asm("mov.b64 %0, {%1, %2};" : "=l"(p) : "f"(f.x), "f"(f.y));
    asm("add.rn.f32x2 %0, %0, %1;" : "+l"(a) : "l"(p));
}

__device__ __forceinline__ void acc_pair(unsigned long long acc[4], uint4 a, uint4 b) {
    __half2 s0 = __hadd2(*(__half2*)&a.x, *(__half2*)&b.x);
    __half2 s1 = __hadd2(*(__half2*)&a.y, *(__half2*)&b.y);
    __half2 s2 = __hadd2(*(__half2*)&a.z, *(__half2*)&b.z);
    __half2 s3 = __hadd2(*(__half2*)&a.w, *(__half2*)&b.w);
    acc_h2(acc[0], s0); acc_h2(acc[1], s1); acc_h2(acc[2], s2); acc_h2(acc[3], s3);
}

__device__ __forceinline__ void acc_one(unsigned long long acc[4], uint4 u) {
    acc_h2(acc[0], *(__half2*)&u.x);
    acc_h2(acc[1], *(__half2*)&u.y);
    acc_h2(acc[2], *(__half2*)&u.z);
    acc_h2(acc[3], *(__half2*)&u.w);
}

__device__ __forceinline__ void unpack8(const unsigned long long acc[4], float o[8]) {
#pragma unroll
    for (int k = 0; k < 4; k++)
        asm("mov.b64 {%0, %1}, %2;" : "=f"(o[2 * k]), "=f"(o[2 * k + 1]) : "l"(acc[k]));
}

// gather: C lanes per node. Indices fetched 4-at-a-time via aligned int4 broadcast;
// 8 independent msg loads in flight per main-loop iteration, no cross-lane deps.
template <int C>
__device__ __forceinline__ void gather_row(unsigned long long acc[4], int n, int c,
                                           const uint4* __restrict__ msg) {
    int beg = __ldg(&g_int[IOFF_ROWP + n]);
    int end = __ldg(&g_int[IOFF_ROWP + n + 1]);
    int i = beg;
    // align i to 4 (csr base is 16B aligned)
    while (i < end && (i & 3)) {
        acc_one(acc, msg[__ldg(&g_int[IOFF_CSR + i]) * C + c]);
        i++;
    }
    // 8 edges per iteration: 2 broadcast int4 idx loads + 8 independent msg loads
    for (; i + 7 < end; i += 8) {
        int4 sa = __ldg((const int4*)&g_int[IOFF_CSR + i]);
        int4 sb = __ldg((const int4*)&g_int[IOFF_CSR + i + 4]);
        uint4 u0 = msg[sa.x * C + c];
        uint4 u1 = msg[sa.y * C + c];
        uint4 u2 = msg[sa.z * C + c];
        uint4 u3 = msg[sa.w * C + c];
        uint4 u4 = msg[sb.x * C + c];
        uint4 u5 = msg[sb.y * C + c];
        uint4 u6 = msg[sb.z * C + c];
        uint4 u7 = msg[sb.w * C + c];
        acc_pair(acc, u0, u1); acc_pair(acc, u2, u3);
        acc_pair(acc, u4, u5); acc_pair(acc, u6, u7);
    }
    if (i + 3 < end) {
        int4 sa = __ldg((const int4*)&g_int[IOFF_CSR + i]);
        uint4 u0 = msg[sa.x * C + c];
        uint4 u1 = msg[sa.y * C + c];
        uint4 u2 = msg[sa.z * C + c];
        uint4 u3 = msg[sa.w * C + c];
        acc_pair(acc, u0, u1); acc_pair(acc, u2, u3);
        i += 4;
    }
    for (; i < end; i++)
        acc_one(acc, msg[__ldg(&g_int[IOFF_CSR + i]) * C + c]);
}

// ---------------- fused layer 1: gather(y1) -> h1 -> p2(fp16) ----------------
// 256 thr = 32 nodes x 8 chunks. W1/W2/b1 via __ldg (L1-resident); smem = sbuf only.

__global__ void __launch_bounds__(256, 6)
k_L1(const float* __restrict__ W1, const float* __restrict__ b1,
     const float* __restrict__ W2) {
    __shared__ float sbuf[32][68];   // agg1, then reused for relu(h1)

    int t = threadIdx.x;
    int ln = t >> 3;
    int c = t & 7;
    int node = blockIdx.x * 32 + ln;
    bool valid = node < NN;

    unsigned long long acc64[4] = {0ULL, 0ULL, 0ULL, 0ULL};
    float nd = 0.0f, ns = 0.0f;
    if (valid) {
        gather_row<8>(acc64, node, c, (const uint4*)(g_half + HOFF_Y1));
        nd = __ldg(&g_work[OFF_NDST + node]);
        ns = __ldg(&g_work[OFF_NSRC + node]);
    }
    float acc[8];
    unpack8(acc64, acc);
#pragma unroll
    for (int j = 0; j < 8; j++) sbuf[ln][c * 8 + j] = acc[j] * nd;
    __syncthreads();

    // h1 = relu(agg1 @ W1 + b1)
    float4 bb0 = __ldg((const float4*)(b1 + c * 8));
    float4 bb1 = __ldg((const float4*)(b1 + c * 8) + 1);
    float h[8] = {bb0.x, bb0.y, bb0.z, bb0.w, bb1.x, bb1.y, bb1.z, bb1.w};
#pragma unroll 8
    for (int k = 0; k < 64; k++) {
        float a = sbuf[ln][k];
        float4 w0 = __ldg((const float4*)(W1 + k * 64 + c * 8));
        float4 w1 = __ldg((const float4*)(W1 + k * 64 + c * 8) + 1);
        h[0] += a * w0.x; h[1] += a * w0.y; h[2] += a * w0.z; h[3] += a * w0.w;
        h[4] += a * w1.x; h[5] += a * w1.y; h[6] += a * w1.z; h[7] += a * w1.w;
    }
    __syncthreads();   // all reads of agg1 done -> reuse buffer
#pragma unroll
    for (int j = 0; j < 8; j++) sbuf[ln][c * 8 + j] = fmaxf(h[j], 0.0f);
    __syncthreads();

    // p2 = (h1 @ W2) * nsrc -> fp16
    float p[4] = {0.f, 0.f, 0.f, 0.f};
#pragma unroll 8
    for (int k = 0; k < 64; k++) {
        float a = sbuf[ln][k];
        float4 w = __ldg((const float4*)(W2 + k * 32 + c * 4));
        p[0] += a * w.x; p[1] += a * w.y; p[2] += a * w.z; p[3] += a * w.w;
    }
    if (valid) {
        __half2 h0 = __floats2half2_rn(p[0] * ns, p[1] * ns);
        __half2 h1v = __floats2half2_rn(p[2] * ns, p[3] * ns);
        uint2 u;
        u.x = *(unsigned*)&h0; u.y = *(unsigned*)&h1v;
        ((uint2*)(g_half + HOFF_P2))[node * 8 + c] = u;
    }
}

// ---------------- fused layer 2: gather(p2) -> embed(out) -> p3(fp16) --------
// 256 thr = 64 nodes x 4 chunks.

__global__ void __launch_bounds__(256, 6)
k_L2(const float* __restrict__ W3, const float* __restrict__ b2,
     float* __restrict__ out_embed) {
    __shared__ float semb[64][36];

    int t = threadIdx.x;
    int ln = t >> 2;
    int c = t & 3;
    int node = blockIdx.x * 64 + ln;
    bool valid = node < NN;

    unsigned long long acc64[4] = {0ULL, 0ULL, 0ULL, 0ULL};
    float nd = 0.0f, ns = 0.0f;
    if (valid) {
        gather_row<4>(acc64, node, c, (const uint4*)(g_half + HOFF_P2));
        nd = __ldg(&g_work[OFF_NDST + node]);
        ns = __ldg(&g_work[OFF_NSRC + node]);
    }
    float acc[8];
    unpack8(acc64, acc);

    float4 bb0 = __ldg((const float4*)(b2 + c * 8));
    float4 bb1 = __ldg((const float4*)(b2 + c * 8) + 1);
    float bv[8] = {bb0.x, bb0.y, bb0.z, bb0.w, bb1.x, bb1.y, bb1.z, bb1.w};
    float e[8];
#pragma unroll
    for (int j = 0; j < 8; j++) {
        e[j] = acc[j] * nd + bv[j];
        semb[ln][c * 8 + j] = fmaxf(e[j], 0.0f);
    }
    if (valid) {
        float4* eo = (float4*)(out_embed + (long)node * 32 + c * 8);
        eo[0] = make_float4(e[0], e[1], e[2], e[3]);
        eo[1] = make_float4(e[4], e[5], e[6], e[7]);
    }
    __syncthreads();

    float p[4] = {0.f, 0.f, 0.f, 0.f};
#pragma unroll 8
    for (int k = 0; k < 32; k++) {
        float a = semb[ln][k];
        float4 w = __ldg((const float4*)(W3 + k * 16 + c * 4));
        p[0] += a * w.x; p[1] += a * w.y; p[2] += a * w.z; p[3] += a * w.w;
    }
    if (valid) {
        __half2 h0 = __floats2half2_rn(p[0] * ns, p[1] * ns);
        __half2 h1v = __floats2half2_rn(p[2] * ns, p[3] * ns);
        uint2 u;
        u.x = *(unsigned*)&h0; u.y = *(unsigned*)&h1v;
        ((uint2*)(g_half + HOFF_P3))[node * 4 + c] = u;
    }
}

// ---------------- layer 3: gather(p3) + epilogue + reset state ----------------

__global__ void k_L3(const float* __restrict__ b3, float* __restrict__ out_h) {
    int t = blockIdx.x * blockDim.x + threadIdx.x;
    int n = t >> 1;
    int c = t & 1;
    if (n < NN) {
        unsigned long long acc64[4] = {0ULL, 0ULL, 0ULL, 0ULL};
        gather_row<2>(acc64, n, c, (const uint4*)(g_half + HOFF_P3));
        float acc[8];
        unpack8(acc64, acc);
        float nd = __ldg(&g_work[OFF_NDST + n]);
        float4 b0 = __ldg((const float4*)b3 + c * 2);
        float4 b1v = __ldg((const float4*)b3 + c * 2 + 1);
        float4* o = (float4*)(out_h + (long)n * 16 + c * 8);
        o[0] = make_float4(acc[0] * nd + b0.x, acc[1] * nd + b0.y,
                           acc[2] * nd + b0.z, acc[3] * nd + b0.w);
        o[1] = make_float4(acc[4] * nd + b1v.x, acc[5] * nd + b1v.y,
                           acc[6] * nd + b1v.z, acc[7] * nd + b1v.w);
    }
    // reset degree counters + scan flags for next call
    if (t < 2 * NN) g_int[t] = 0;
    if (t < 256) g_status[t] = 0ULL;
}

// ---------------- launch ----------------

extern "C" void kernel_launch(void* const* d_in, const int* in_sizes, int n_in,
                              void* d_out, int out_size) {
    const float* x  = (const float*)d_in[0];
    const float* W1 = (const float*)d_in[1];
    const float* b1 = (const float*)d_in[2];
    const float* W2 = (const float*)d_in[3];
    const float* b2 = (const float*)d_in[4];
    const float* W3 = (const float*)d_in[5];
    const float* b3 = (const float*)d_in[6];
    const int* src  = (const int*)d_in[7];
    const int* dst  = (const int*)d_in[8];
    float* out = (float*)d_out;
    int E = in_sizes[7];
    (void)n_in; (void)out_size;

    const int TB = 256;
    auto blk = [](long n, int tb) { return (int)((n + tb - 1) / tb); };

    k_deg<<<blk((E + 3) / 4, TB), TB>>>(src, dst, E);
    k_scan_norm<<<NB, 256>>>(x);
    k_fill<<<blk((E + 3) / 4, TB), TB>>>(src, dst, E);
    k_L1<<<blk(NN, 32), 256>>>(W1, b1, W2);
    k_L2<<<blk(NN, 64), 256>>>(W3, b2, out);
    k_L3<<<blk((long)NN * 2, TB), TB>>>(b3, out + 32 * NN);
}